// round 1
// baseline (speedup 1.0000x reference)
#include <cuda_runtime.h>
#include <cuda_bf16.h>

#define Nn   50000
#define Ee   800000
#define F_IN 128
#define HID  64
#define Ll   3
#define Gg   512
#define BN_EPS 1e-5f

// ---------------- scratch (static device arrays; no runtime allocation) ----
__device__ float g_h[Nn * HID];     // activations (post-relu)
__device__ float g_z[Nn * HID];     // post-linear (BN folded)
__device__ float g_out[Nn * HID];   // aggregation accumulator
__device__ float g_Wp[F_IN * HID];  // folded weight (max 128x64)
__device__ float g_c[HID];          // folded bias row
__device__ float g_sum[F_IN];
__device__ float g_sumsq[F_IN];
__device__ int   g_deg[Nn];
__device__ float g_dis[Nn];

// ---------------- small utility kernels ------------------------------------
__global__ void zero_stats_kernel() {
    int t = threadIdx.x;
    if (t < F_IN) { g_sum[t] = 0.f; g_sumsq[t] = 0.f; }
}

__global__ void zero_deg_kernel() {
    int v = blockIdx.x * blockDim.x + threadIdx.x;
    if (v < Nn) g_deg[v] = 0;
}

__global__ void deg_kernel(const int* __restrict__ src) {
    int e = blockIdx.x * blockDim.x + threadIdx.x;
    if (e < Ee) atomicAdd(&g_deg[src[e]], 1);
}

__global__ void dis_kernel() {
    int v = blockIdx.x * blockDim.x + threadIdx.x;
    if (v < Nn) g_dis[v] = rsqrtf((float)(g_deg[v] + 1));  // +1 self loop
}

// ---------------- column stats (+ optional bias+relu finish) ---------------
// blockDim = (C, 256/C). mode: in -> v = relu?(in+bias); optional write hout.
__global__ void stats_kernel(const float* __restrict__ in,
                             const float* __restrict__ bias,
                             float* __restrict__ hout,
                             int n, int C, int doRelu) {
    int col = threadIdx.x;
    int yr  = threadIdx.y;
    int R   = blockDim.y;
    float b = bias ? bias[col] : 0.f;
    float s = 0.f, ss = 0.f;
    for (int r = blockIdx.x * R + yr; r < n; r += gridDim.x * R) {
        float v = in[(long)r * C + col] + b;
        if (doRelu) v = fmaxf(v, 0.f);
        if (hout) hout[(long)r * C + col] = v;
        s += v; ss += v * v;
    }
    __shared__ float sh0[256], sh1[256];
    sh0[yr * C + col] = s;
    sh1[yr * C + col] = ss;
    __syncthreads();
    if (yr == 0) {
        for (int j = 1; j < R; j++) { s += sh0[j * C + col]; ss += sh1[j * C + col]; }
        atomicAdd(&g_sum[col], s);
        atomicAdd(&g_sumsq[col], ss);
    }
}

// ---------------- fold BN into weights: Wp = diag(s)W, c = t@W (+blin) -----
__global__ void fold_kernel(const float* __restrict__ gamma,
                            const float* __restrict__ beta,
                            const float* __restrict__ W,     // [K][64]
                            const float* __restrict__ blin,  // or null
                            int K, float invN) {
    __shared__ float s_s[F_IN], s_t[F_IN];
    int t = threadIdx.x;
    if (t < K) {
        float mu  = g_sum[t] * invN;
        float var = fmaxf(g_sumsq[t] * invN - mu * mu, 0.f);
        float sc  = gamma[t] * rsqrtf(var + BN_EPS);
        s_s[t] = sc;
        s_t[t] = beta[t] - mu * sc;
    }
    __syncthreads();
    for (int i = t; i < K * HID; i += blockDim.x)
        g_Wp[i] = s_s[i >> 6] * W[i];
    if (t < HID) {
        float c = blin ? blin[t] : 0.f;
        for (int k = 0; k < K; k++) c += s_t[k] * W[k * HID + t];
        g_c[t] = c;
    }
}

// ---------------- tiled GEMM: 64x64 tiles, 4x4 register tiles --------------
// FEAT : g_h = relu(A @ Wp + c)
// LAYER: g_z = A @ Wp + c ; g_out = dis^2 * g_z  (self-loop init)
template <int K, bool FEAT>
__global__ void __launch_bounds__(256)
gemm_kernel(const float* __restrict__ A, int n) {
    __shared__ float As[64 * 64];
    __shared__ float Wsm[64 * 64];
    const int t  = threadIdx.x;
    const int tx = t & 15;
    const int ty = t >> 4;
    const int rowBase = blockIdx.x * 64;

    float4 acc0 = {0,0,0,0}, acc1 = {0,0,0,0}, acc2 = {0,0,0,0}, acc3 = {0,0,0,0};

    for (int kt = 0; kt < K; kt += 64) {
        #pragma unroll
        for (int i = t; i < 64 * 16; i += 256) {
            int r = i >> 4, c4 = i & 15;
            int gr = rowBase + r;
            float4 v = {0,0,0,0};
            if (gr < n) v = *(const float4*)(A + (long)gr * K + kt + 4 * c4);
            ((float4*)As)[i] = v;
        }
        #pragma unroll
        for (int i = t; i < 64 * 16; i += 256) {
            int r = i >> 4, c4 = i & 15;
            ((float4*)Wsm)[i] = *(const float4*)(g_Wp + (long)(kt + r) * 64 + 4 * c4);
        }
        __syncthreads();

        #pragma unroll
        for (int k4 = 0; k4 < 64; k4 += 4) {
            float4 a0 = ((const float4*)As)[(4 * ty + 0) * 16 + (k4 >> 2)];
            float4 a1 = ((const float4*)As)[(4 * ty + 1) * 16 + (k4 >> 2)];
            float4 a2 = ((const float4*)As)[(4 * ty + 2) * 16 + (k4 >> 2)];
            float4 a3 = ((const float4*)As)[(4 * ty + 3) * 16 + (k4 >> 2)];
            float4 w0 = ((const float4*)Wsm)[(k4 + 0) * 16 + tx];
            float4 w1 = ((const float4*)Wsm)[(k4 + 1) * 16 + tx];
            float4 w2 = ((const float4*)Wsm)[(k4 + 2) * 16 + tx];
            float4 w3 = ((const float4*)Wsm)[(k4 + 3) * 16 + tx];
            #define FMA4(ACC, AV)                                              \
                ACC.x += AV.x * w0.x; ACC.y += AV.x * w0.y;                    \
                ACC.z += AV.x * w0.z; ACC.w += AV.x * w0.w;                    \
                ACC.x += AV.y * w1.x; ACC.y += AV.y * w1.y;                    \
                ACC.z += AV.y * w1.z; ACC.w += AV.y * w1.w;                    \
                ACC.x += AV.z * w2.x; ACC.y += AV.z * w2.y;                    \
                ACC.z += AV.z * w2.z; ACC.w += AV.z * w2.w;                    \
                ACC.x += AV.w * w3.x; ACC.y += AV.w * w3.y;                    \
                ACC.z += AV.w * w3.z; ACC.w += AV.w * w3.w;
            FMA4(acc0, a0) FMA4(acc1, a1) FMA4(acc2, a2) FMA4(acc3, a3)
            #undef FMA4
        }
        __syncthreads();
    }

    float4 cv = *(const float4*)(g_c + 4 * tx);
    float4 accs[4] = {acc0, acc1, acc2, acc3};
    #pragma unroll
    for (int i = 0; i < 4; i++) {
        int gr = rowBase + 4 * ty + i;
        if (gr >= n) continue;
        float4 v = accs[i];
        v.x += cv.x; v.y += cv.y; v.z += cv.z; v.w += cv.w;
        if (FEAT) {
            v.x = fmaxf(v.x, 0.f); v.y = fmaxf(v.y, 0.f);
            v.z = fmaxf(v.z, 0.f); v.w = fmaxf(v.w, 0.f);
            *(float4*)(g_h + (long)gr * 64 + 4 * tx) = v;
        } else {
            *(float4*)(g_z + (long)gr * 64 + 4 * tx) = v;
            float dd = g_dis[gr]; dd = dd * dd;
            float4 o = {dd * v.x, dd * v.y, dd * v.z, dd * v.w};
            *(float4*)(g_out + (long)gr * 64 + 4 * tx) = o;
        }
    }
}

// ---------------- edge gather/scatter ---------------------------------------
__global__ void edge_agg_kernel(const int* __restrict__ src,
                                const int* __restrict__ dst) {
    long gid = (long)blockIdx.x * blockDim.x + threadIdx.x;
    int e = (int)(gid >> 4);
    if (e >= Ee) return;
    int c = ((int)gid & 15) * 4;
    int s = __ldg(src + e);
    int d = __ldg(dst + e);
    float w = __ldg(g_dis + s) * __ldg(g_dis + d);
    float4 v = *(const float4*)(g_z + (long)s * 64 + c);
    float* o = g_out + (long)d * 64 + c;
    atomicAdd(o + 0, w * v.x);
    atomicAdd(o + 1, w * v.y);
    atomicAdd(o + 2, w * v.z);
    atomicAdd(o + 3, w * v.w);
}

// ---------------- pooling ----------------------------------------------------
__global__ void pool_kernel(const int* __restrict__ batch,
                            const float* __restrict__ b2,
                            float* __restrict__ gout) {
    long gid = (long)blockIdx.x * blockDim.x + threadIdx.x;
    int node = (int)(gid >> 4);
    if (node >= Nn) return;
    int c = ((int)gid & 15) * 4;
    int g = __ldg(batch + node);
    float4 v = *(const float4*)(g_out + (long)node * 64 + c);
    float4 bb = *(const float4*)(b2 + c);
    float* o = gout + (long)g * 64 + c;
    atomicAdd(o + 0, fmaxf(v.x + bb.x, 0.f));
    atomicAdd(o + 1, fmaxf(v.y + bb.y, 0.f));
    atomicAdd(o + 2, fmaxf(v.z + bb.z, 0.f));
    atomicAdd(o + 3, fmaxf(v.w + bb.w, 0.f));
}

// ---------------- host-side symbol resolution (no allocation) --------------
static float* sym_h() {
    static float* p = nullptr;
    if (!p) cudaGetSymbolAddress((void**)&p, g_h);
    return p;
}
static float* sym_out() {
    static float* p = nullptr;
    if (!p) cudaGetSymbolAddress((void**)&p, g_out);
    return p;
}

// ---------------- launch ----------------------------------------------------
extern "C" void kernel_launch(void* const* d_in, const int* in_sizes, int n_in,
                              void* d_out, int out_size) {
    const float* x         = (const float*)d_in[0];
    const int*   ei        = (const int*)d_in[1];
    const int*   src       = ei;
    const int*   dst       = ei + Ee;
    const int*   batch     = (const int*)d_in[2];
    const float* bn_feat_g = (const float*)d_in[3];
    const float* bn_feat_b = (const float*)d_in[4];
    const float* W_feat    = (const float*)d_in[5];
    const float* b_feat    = (const float*)d_in[6];
    const float* bn_g      = (const float*)d_in[7];
    const float* bn_b      = (const float*)d_in[8];
    const float* Ws        = (const float*)d_in[9];
    const float* bs        = (const float*)d_in[10];
    float* gout = (float*)d_out;

    const int gemm_blocks = (Nn + 63) / 64;
    const float invN = 1.0f / (float)Nn;

    // degree / dis (independent of activations)
    zero_deg_kernel<<<(Nn + 255) / 256, 256>>>();
    deg_kernel<<<(Ee + 255) / 256, 256>>>(src);
    dis_kernel<<<(Nn + 255) / 256, 256>>>();

    // feature BN stats + fold + linear(relu)
    zero_stats_kernel<<<1, 256>>>();
    {
        dim3 b(F_IN, 256 / F_IN);
        stats_kernel<<<256, b>>>(x, nullptr, nullptr, Nn, F_IN, 0);
    }
    fold_kernel<<<1, 256>>>(bn_feat_g, bn_feat_b, W_feat, b_feat, F_IN, invN);
    gemm_kernel<F_IN, true><<<gemm_blocks, 256>>>(x, Nn);

    // 3 GCN layers
    for (int i = 0; i < Ll; i++) {
        zero_stats_kernel<<<1, 256>>>();
        {
            dim3 b(HID, 256 / HID);
            if (i == 0)
                stats_kernel<<<256, b>>>(sym_h(), nullptr, nullptr, Nn, HID, 1);
            else
                stats_kernel<<<256, b>>>(sym_out(), bs + (i - 1) * HID,
                                         sym_h(), Nn, HID, 1);
        }
        fold_kernel<<<1, 256>>>(bn_g + i * HID, bn_b + i * HID,
                                Ws + (long)i * HID * HID, nullptr, HID, invN);
        gemm_kernel<HID, false><<<gemm_blocks, 256>>>(sym_h(), Nn);
        edge_agg_kernel<<<(int)(((long)Ee * 16 + 255) / 256), 256>>>(src, dst);
    }

    // pooling
    cudaMemsetAsync(gout, 0, (size_t)Gg * HID * sizeof(float));
    pool_kernel<<<(int)(((long)Nn * 16 + 255) / 256), 256>>>(batch, bs + 2 * HID, gout);
}

// round 2
// speedup vs baseline: 1.5913x; 1.5913x over previous
#include <cuda_runtime.h>
#include <cuda_bf16.h>

#define Nn   50000
#define Ee   800000
#define F_IN 128
#define HID  64
#define Ll   3
#define Gg   512
#define BN_EPS 1e-5f

// ---------------- scratch (static device arrays; no runtime allocation) ----
__device__ float g_h[Nn * HID];     // activations (post-relu)
__device__ float g_z[Nn * HID];     // post-linear (BN folded)
__device__ float g_out[Nn * HID];   // aggregation accumulator
__device__ float g_Wp[F_IN * HID];  // folded weight (max 128x64)
__device__ float g_c[HID];          // folded bias row
__device__ float g_sum[F_IN];
__device__ float g_sumsq[F_IN];
__device__ int   g_deg[Nn];
__device__ float g_dis[Nn];

// ---------------- small utility kernels ------------------------------------
__global__ void zero_stats_kernel() {
    int t = threadIdx.x;
    if (t < F_IN) { g_sum[t] = 0.f; g_sumsq[t] = 0.f; }
}

__global__ void zero_deg_kernel() {
    int v = blockIdx.x * blockDim.x + threadIdx.x;
    if (v < Nn) g_deg[v] = 0;
}

__global__ void deg_kernel(const int* __restrict__ src) {
    int e = blockIdx.x * blockDim.x + threadIdx.x;
    if (e < Ee) atomicAdd(&g_deg[src[e]], 1);
}

__global__ void dis_kernel() {
    int v = blockIdx.x * blockDim.x + threadIdx.x;
    if (v < Nn) g_dis[v] = rsqrtf((float)(g_deg[v] + 1));  // +1 self loop
}

// ---------------- column stats (+ optional bias+relu finish) ---------------
// blockDim = (C, 256/C). v = relu?(in+bias); optional write hout.
__global__ void stats_kernel(const float* __restrict__ in,
                             const float* __restrict__ bias,
                             float* __restrict__ hout,
                             int n, int C, int doRelu) {
    int col = threadIdx.x;
    int yr  = threadIdx.y;
    int R   = blockDim.y;
    float b = bias ? bias[col] : 0.f;
    float s = 0.f, ss = 0.f;
    for (int r = blockIdx.x * R + yr; r < n; r += gridDim.x * R) {
        float v = in[(long)r * C + col] + b;
        if (doRelu) v = fmaxf(v, 0.f);
        if (hout) hout[(long)r * C + col] = v;
        s += v; ss += v * v;
    }
    __shared__ float sh0[256], sh1[256];
    sh0[yr * C + col] = s;
    sh1[yr * C + col] = ss;
    __syncthreads();
    if (yr == 0) {
        for (int j = 1; j < R; j++) { s += sh0[j * C + col]; ss += sh1[j * C + col]; }
        atomicAdd(&g_sum[col], s);
        atomicAdd(&g_sumsq[col], ss);
    }
}

// ---------------- fold BN into weights: Wp = diag(s)W, c = t@W (+blin) -----
__global__ void fold_kernel(const float* __restrict__ gamma,
                            const float* __restrict__ beta,
                            const float* __restrict__ W,     // [K][64]
                            const float* __restrict__ blin,  // or null
                            int K, float invN) {
    __shared__ float s_s[F_IN], s_t[F_IN];
    int t = threadIdx.x;
    if (t < K) {
        float mu  = g_sum[t] * invN;
        float var = fmaxf(g_sumsq[t] * invN - mu * mu, 0.f);
        float sc  = gamma[t] * rsqrtf(var + BN_EPS);
        s_s[t] = sc;
        s_t[t] = beta[t] - mu * sc;
    }
    __syncthreads();
    for (int i = t; i < K * HID; i += blockDim.x)
        g_Wp[i] = s_s[i >> 6] * W[i];
    if (t < HID) {
        float c = blin ? blin[t] : 0.f;
        for (int k = 0; k < K; k++) c += s_t[k] * W[k * HID + t];
        g_c[t] = c;
    }
}

// ---------------- tiled GEMM: 64x64 tiles, 4x4 register tiles --------------
// FEAT : g_h = relu(A @ Wp + c)
// LAYER: g_z = A @ Wp + c ; g_out = dis^2 * g_z  (self-loop init)
template <int K, bool FEAT>
__global__ void __launch_bounds__(256)
gemm_kernel(const float* __restrict__ A, int n) {
    __shared__ float As[64 * 64];
    __shared__ float Wsm[64 * 64];
    const int t  = threadIdx.x;
    const int tx = t & 15;
    const int ty = t >> 4;
    const int rowBase = blockIdx.x * 64;

    float4 acc0 = {0,0,0,0}, acc1 = {0,0,0,0}, acc2 = {0,0,0,0}, acc3 = {0,0,0,0};

    for (int kt = 0; kt < K; kt += 64) {
        #pragma unroll
        for (int i = t; i < 64 * 16; i += 256) {
            int r = i >> 4, c4 = i & 15;
            int gr = rowBase + r;
            float4 v = {0,0,0,0};
            if (gr < n) v = *(const float4*)(A + (long)gr * K + kt + 4 * c4);
            ((float4*)As)[i] = v;
        }
        #pragma unroll
        for (int i = t; i < 64 * 16; i += 256) {
            int r = i >> 4, c4 = i & 15;
            ((float4*)Wsm)[i] = *(const float4*)(g_Wp + (long)(kt + r) * 64 + 4 * c4);
        }
        __syncthreads();

        #pragma unroll
        for (int k4 = 0; k4 < 64; k4 += 4) {
            float4 a0 = ((const float4*)As)[(4 * ty + 0) * 16 + (k4 >> 2)];
            float4 a1 = ((const float4*)As)[(4 * ty + 1) * 16 + (k4 >> 2)];
            float4 a2 = ((const float4*)As)[(4 * ty + 2) * 16 + (k4 >> 2)];
            float4 a3 = ((const float4*)As)[(4 * ty + 3) * 16 + (k4 >> 2)];
            float4 w0 = ((const float4*)Wsm)[(k4 + 0) * 16 + tx];
            float4 w1 = ((const float4*)Wsm)[(k4 + 1) * 16 + tx];
            float4 w2 = ((const float4*)Wsm)[(k4 + 2) * 16 + tx];
            float4 w3 = ((const float4*)Wsm)[(k4 + 3) * 16 + tx];
            #define FMA4(ACC, AV)                                              \
                ACC.x += AV.x * w0.x; ACC.y += AV.x * w0.y;                    \
                ACC.z += AV.x * w0.z; ACC.w += AV.x * w0.w;                    \
                ACC.x += AV.y * w1.x; ACC.y += AV.y * w1.y;                    \
                ACC.z += AV.y * w1.z; ACC.w += AV.y * w1.w;                    \
                ACC.x += AV.z * w2.x; ACC.y += AV.z * w2.y;                    \
                ACC.z += AV.z * w2.z; ACC.w += AV.z * w2.w;                    \
                ACC.x += AV.w * w3.x; ACC.y += AV.w * w3.y;                    \
                ACC.z += AV.w * w3.z; ACC.w += AV.w * w3.w;
            FMA4(acc0, a0) FMA4(acc1, a1) FMA4(acc2, a2) FMA4(acc3, a3)
            #undef FMA4
        }
        __syncthreads();
    }

    float4 cv = *(const float4*)(g_c + 4 * tx);
    float4 accs[4] = {acc0, acc1, acc2, acc3};
    #pragma unroll
    for (int i = 0; i < 4; i++) {
        int gr = rowBase + 4 * ty + i;
        if (gr >= n) continue;
        float4 v = accs[i];
        v.x += cv.x; v.y += cv.y; v.z += cv.z; v.w += cv.w;
        if (FEAT) {
            v.x = fmaxf(v.x, 0.f); v.y = fmaxf(v.y, 0.f);
            v.z = fmaxf(v.z, 0.f); v.w = fmaxf(v.w, 0.f);
            *(float4*)(g_h + (long)gr * 64 + 4 * tx) = v;
        } else {
            *(float4*)(g_z + (long)gr * 64 + 4 * tx) = v;
            float dd = g_dis[gr]; dd = dd * dd;
            float4 o = {dd * v.x, dd * v.y, dd * v.z, dd * v.w};
            *(float4*)(g_out + (long)gr * 64 + 4 * tx) = o;
        }
    }
}

// ---------------- vectorized global reduction helper ------------------------
__device__ __forceinline__ void red_add_v4(float* addr, float4 v) {
    asm volatile("red.global.add.v4.f32 [%0], {%1, %2, %3, %4};"
                 :: "l"(addr), "f"(v.x), "f"(v.y), "f"(v.z), "f"(v.w)
                 : "memory");
}

// ---------------- edge gather/scatter ---------------------------------------
// out[dst] += dis[src]*dis[dst] * z[src]   (one red.v4 per 4 columns)
__global__ void edge_agg_kernel(const int* __restrict__ src,
                                const int* __restrict__ dst) {
    long gid = (long)blockIdx.x * blockDim.x + threadIdx.x;
    int e = (int)(gid >> 4);
    if (e >= Ee) return;
    int c = ((int)gid & 15) * 4;
    int s = __ldg(src + e);
    int d = __ldg(dst + e);
    float w = __ldg(g_dis + s) * __ldg(g_dis + d);
    float4 v = *(const float4*)(g_z + (long)s * 64 + c);
    float4 r = {w * v.x, w * v.y, w * v.z, w * v.w};
    red_add_v4(g_out + (long)d * 64 + c, r);
}

// ---------------- pooling ----------------------------------------------------
__global__ void pool_kernel(const int* __restrict__ batch,
                            const float* __restrict__ b2,
                            float* __restrict__ gout) {
    long gid = (long)blockIdx.x * blockDim.x + threadIdx.x;
    int node = (int)(gid >> 4);
    if (node >= Nn) return;
    int c = ((int)gid & 15) * 4;
    int g = __ldg(batch + node);
    float4 v = *(const float4*)(g_out + (long)node * 64 + c);
    float4 bb = *(const float4*)(b2 + c);
    float4 r = {fmaxf(v.x + bb.x, 0.f), fmaxf(v.y + bb.y, 0.f),
                fmaxf(v.z + bb.z, 0.f), fmaxf(v.w + bb.w, 0.f)};
    red_add_v4(gout + (long)g * 64 + c, r);
}

// ---------------- host-side symbol resolution (no allocation) --------------
static float* sym_h() {
    static float* p = nullptr;
    if (!p) cudaGetSymbolAddress((void**)&p, g_h);
    return p;
}
static float* sym_out() {
    static float* p = nullptr;
    if (!p) cudaGetSymbolAddress((void**)&p, g_out);
    return p;
}

// ---------------- launch ----------------------------------------------------
extern "C" void kernel_launch(void* const* d_in, const int* in_sizes, int n_in,
                              void* d_out, int out_size) {
    const float* x         = (const float*)d_in[0];
    const int*   ei        = (const int*)d_in[1];
    const int*   src       = ei;
    const int*   dst       = ei + Ee;
    const int*   batch     = (const int*)d_in[2];
    const float* bn_feat_g = (const float*)d_in[3];
    const float* bn_feat_b = (const float*)d_in[4];
    const float* W_feat    = (const float*)d_in[5];
    const float* b_feat    = (const float*)d_in[6];
    const float* bn_g      = (const float*)d_in[7];
    const float* bn_b      = (const float*)d_in[8];
    const float* Ws        = (const float*)d_in[9];
    const float* bs        = (const float*)d_in[10];
    float* gout = (float*)d_out;

    const int gemm_blocks = (Nn + 63) / 64;
    const float invN = 1.0f / (float)Nn;

    // degree / dis (independent of activations)
    zero_deg_kernel<<<(Nn + 255) / 256, 256>>>();
    deg_kernel<<<(Ee + 255) / 256, 256>>>(src);
    dis_kernel<<<(Nn + 255) / 256, 256>>>();

    // feature BN stats + fold + linear(relu)
    zero_stats_kernel<<<1, 256>>>();
    {
        dim3 b(F_IN, 256 / F_IN);
        stats_kernel<<<256, b>>>(x, nullptr, nullptr, Nn, F_IN, 0);
    }
    fold_kernel<<<1, 256>>>(bn_feat_g, bn_feat_b, W_feat, b_feat, F_IN, invN);
    gemm_kernel<F_IN, true><<<gemm_blocks, 256>>>(x, Nn);

    // 3 GCN layers
    for (int i = 0; i < Ll; i++) {
        zero_stats_kernel<<<1, 256>>>();
        {
            dim3 b(HID, 256 / HID);
            if (i == 0)
                stats_kernel<<<256, b>>>(sym_h(), nullptr, nullptr, Nn, HID, 1);
            else
                stats_kernel<<<256, b>>>(sym_out(), bs + (i - 1) * HID,
                                         sym_h(), Nn, HID, 1);
        }
        fold_kernel<<<1, 256>>>(bn_g + i * HID, bn_b + i * HID,
                                Ws + (long)i * HID * HID, nullptr, HID, invN);
        gemm_kernel<HID, false><<<gemm_blocks, 256>>>(sym_h(), Nn);
        edge_agg_kernel<<<(int)(((long)Ee * 16 + 255) / 256), 256>>>(src, dst);
    }

    // pooling
    cudaMemsetAsync(gout, 0, (size_t)Gg * HID * sizeof(float));
    pool_kernel<<<(int)(((long)Nn * 16 + 255) / 256), 256>>>(batch, bs + 2 * HID, gout);
}

// round 3
// speedup vs baseline: 1.7581x; 1.1048x over previous
#include <cuda_runtime.h>
#include <cuda_bf16.h>

#define Nn   50000
#define Ee   800000
#define F_IN 128
#define HID  64
#define Ll   3
#define Gg   512
#define BN_EPS 1e-5f

#define GEMM_BLOCKS   ((Nn + 63) / 64)       // 782
#define GATHER_BLOCKS 512
#define SCAN_T   512
#define SCAN_E   2048
#define SCAN_NB  ((Nn + SCAN_E - 1) / SCAN_E)  // 25

// ---------------- scratch (static device arrays) ----------------------------
__device__ float g_h[Nn * HID];        // activations (post-relu)
__device__ float g_z[Nn * HID];        // post-linear (BN folded)
__device__ float g_Wp[F_IN * HID];     // folded weight
__device__ float g_c[HID];             // folded bias row
__device__ float g_sum[F_IN];          // atomic stats (x only)
__device__ float g_sumsq[F_IN];
__device__ int   g_degout[Nn];
__device__ int   g_degin[Nn];
__device__ float g_dis[Nn];
__device__ int   g_off[Nn + 1];
__device__ int   g_cursor[Nn];
__device__ int   g_csr[Ee];
__device__ int   g_bsum[SCAN_NB];
__device__ int   g_bbase[SCAN_NB];
__device__ float g_psum[1024 * HID];   // per-block partial stats
__device__ float g_psq[1024 * HID];

// ---------------- helpers ----------------------------------------------------
__device__ __forceinline__ void red_add_v4(float* addr, float4 v) {
    asm volatile("red.global.add.v4.f32 [%0], {%1, %2, %3, %4};"
                 :: "l"(addr), "f"(v.x), "f"(v.y), "f"(v.z), "f"(v.w)
                 : "memory");
}

// ---------------- setup kernels ----------------------------------------------
__global__ void zero_all_kernel() {
    int v = blockIdx.x * blockDim.x + threadIdx.x;
    if (v < Nn) { g_degout[v] = 0; g_degin[v] = 0; }
    if (v < F_IN) { g_sum[v] = 0.f; g_sumsq[v] = 0.f; }
}

__global__ void count_kernel(const int* __restrict__ src,
                             const int* __restrict__ dst) {
    int e = blockIdx.x * blockDim.x + threadIdx.x;
    if (e < Ee) {
        atomicAdd(&g_degout[src[e]], 1);
        atomicAdd(&g_degin[dst[e]], 1);
    }
}

__global__ void dis_kernel() {
    int v = blockIdx.x * blockDim.x + threadIdx.x;
    if (v < Nn) g_dis[v] = rsqrtf((float)(g_degout[v] + 1));
}

// ---- hierarchical exclusive scan over g_degin -> g_off ----------------------
__global__ void scan1_kernel() {   // per-block sums
    __shared__ int sh[SCAN_T];
    int t = threadIdx.x, b = blockIdx.x;
    int s = 0;
    #pragma unroll
    for (int j = 0; j < 4; j++) {
        int i = b * SCAN_E + t + j * SCAN_T;
        if (i < Nn) s += g_degin[i];
    }
    sh[t] = s; __syncthreads();
    for (int o = SCAN_T / 2; o > 0; o >>= 1) {
        if (t < o) sh[t] += sh[t + o];
        __syncthreads();
    }
    if (t == 0) g_bsum[b] = sh[0];
}

__global__ void scan2_kernel() {   // exclusive scan of block sums
    if (threadIdx.x == 0) {
        int acc = 0;
        for (int b = 0; b < SCAN_NB; b++) { g_bbase[b] = acc; acc += g_bsum[b]; }
        g_off[Nn] = acc;   // == Ee
    }
}

__global__ void scan3_kernel() {   // local scan + base -> offsets + cursor
    __shared__ int sh[SCAN_T];
    int t = threadIdx.x, b = blockIdx.x;
    int base = b * SCAN_E + t * 4;
    int d0 = 0, d1 = 0, d2 = 0, d3 = 0;
    if (base + 0 < Nn) d0 = g_degin[base + 0];
    if (base + 1 < Nn) d1 = g_degin[base + 1];
    if (base + 2 < Nn) d2 = g_degin[base + 2];
    if (base + 3 < Nn) d3 = g_degin[base + 3];
    int tsum = d0 + d1 + d2 + d3;
    sh[t] = tsum; __syncthreads();
    // Hillis-Steele inclusive scan
    for (int o = 1; o < SCAN_T; o <<= 1) {
        int v = (t >= o) ? sh[t - o] : 0;
        __syncthreads();
        sh[t] += v;
        __syncthreads();
    }
    int excl = sh[t] - tsum + g_bbase[b];
    int o0 = excl, o1 = o0 + d0, o2 = o1 + d1, o3 = o2 + d2;
    if (base + 0 < Nn) { g_off[base + 0] = o0; g_cursor[base + 0] = o0; }
    if (base + 1 < Nn) { g_off[base + 1] = o1; g_cursor[base + 1] = o1; }
    if (base + 2 < Nn) { g_off[base + 2] = o2; g_cursor[base + 2] = o2; }
    if (base + 3 < Nn) { g_off[base + 3] = o3; g_cursor[base + 3] = o3; }
}

__global__ void fill_kernel(const int* __restrict__ src,
                            const int* __restrict__ dst) {
    int e = blockIdx.x * blockDim.x + threadIdx.x;
    if (e < Ee) {
        int pos = atomicAdd(&g_cursor[dst[e]], 1);
        g_csr[pos] = src[e];
    }
}

// ---------------- stats over x (atomic; g_sum zeroed in zero_all) -----------
__global__ void stats_x_kernel(const float* __restrict__ in) {
    int col = threadIdx.x;           // 128
    int yr  = threadIdx.y;           // 2
    float s = 0.f, ss = 0.f;
    for (int r = blockIdx.x * 2 + yr; r < Nn; r += gridDim.x * 2) {
        float v = in[(long)r * F_IN + col];
        s += v; ss += v * v;
    }
    __shared__ float sh0[256], sh1[256];
    sh0[yr * F_IN + col] = s;
    sh1[yr * F_IN + col] = ss;
    __syncthreads();
    if (yr == 0) {
        s += sh0[F_IN + col]; ss += sh1[F_IN + col];
        atomicAdd(&g_sum[col], s);
        atomicAdd(&g_sumsq[col], ss);
    }
}

// ---------------- fold: BN -> (Wp, c). Stats from atomics or partials. ------
__global__ void fold_kernel(const float* __restrict__ gamma,
                            const float* __restrict__ beta,
                            const float* __restrict__ W,     // [K][64]
                            const float* __restrict__ blin,  // or null
                            int K, float invN, int nPart) {
    __shared__ float s_s[F_IN], s_t[F_IN];
    __shared__ float redS[256], redQ[256];
    int t = threadIdx.x;
    if (nPart > 0) {    // K == 64 path
        int col = t & 63, grp = t >> 6;
        float s = 0.f, q = 0.f;
        for (int p = grp; p < nPart; p += 4) {
            s += g_psum[p * 64 + col];
            q += g_psq[p * 64 + col];
        }
        redS[t] = s; redQ[t] = q;
        __syncthreads();
        if (grp == 0) {
            s += redS[64 + col] + redS[128 + col] + redS[192 + col];
            q += redQ[64 + col] + redQ[128 + col] + redQ[192 + col];
            float mu  = s * invN;
            float var = fmaxf(q * invN - mu * mu, 0.f);
            float sc  = gamma[col] * rsqrtf(var + BN_EPS);
            s_s[col] = sc;
            s_t[col] = beta[col] - mu * sc;
        }
    } else {
        if (t < K) {
            float mu  = g_sum[t] * invN;
            float var = fmaxf(g_sumsq[t] * invN - mu * mu, 0.f);
            float sc  = gamma[t] * rsqrtf(var + BN_EPS);
            s_s[t] = sc;
            s_t[t] = beta[t] - mu * sc;
        }
    }
    __syncthreads();
    for (int i = t; i < K * HID; i += blockDim.x)
        g_Wp[i] = s_s[i >> 6] * W[i];
    if (t < HID) {
        float c = blin ? blin[t] : 0.f;
        for (int k = 0; k < K; k++) c += s_t[k] * W[k * HID + t];
        g_c[t] = c;
    }
}

// ---------------- tiled GEMM -------------------------------------------------
// FEAT : g_h = relu(A @ Wp + c), accumulate per-block partial stats of h.
// LAYER: g_z = A @ Wp + c.
template <int K, bool FEAT>
__global__ void __launch_bounds__(256)
gemm_kernel(const float* __restrict__ A, int n) {
    __shared__ float As[64 * 64];
    __shared__ float Wsm[64 * 64];
    const int t  = threadIdx.x;
    const int tx = t & 15;
    const int ty = t >> 4;
    const int rowBase = blockIdx.x * 64;

    float4 acc0 = {0,0,0,0}, acc1 = {0,0,0,0}, acc2 = {0,0,0,0}, acc3 = {0,0,0,0};

    for (int kt = 0; kt < K; kt += 64) {
        #pragma unroll
        for (int i = t; i < 64 * 16; i += 256) {
            int r = i >> 4, c4 = i & 15;
            int gr = rowBase + r;
            float4 v = {0,0,0,0};
            if (gr < n) v = *(const float4*)(A + (long)gr * K + kt + 4 * c4);
            ((float4*)As)[i] = v;
        }
        #pragma unroll
        for (int i = t; i < 64 * 16; i += 256) {
            int r = i >> 4, c4 = i & 15;
            ((float4*)Wsm)[i] = *(const float4*)(g_Wp + (long)(kt + r) * 64 + 4 * c4);
        }
        __syncthreads();

        #pragma unroll
        for (int k4 = 0; k4 < 64; k4 += 4) {
            float4 a0 = ((const float4*)As)[(4 * ty + 0) * 16 + (k4 >> 2)];
            float4 a1 = ((const float4*)As)[(4 * ty + 1) * 16 + (k4 >> 2)];
            float4 a2 = ((const float4*)As)[(4 * ty + 2) * 16 + (k4 >> 2)];
            float4 a3 = ((const float4*)As)[(4 * ty + 3) * 16 + (k4 >> 2)];
            float4 w0 = ((const float4*)Wsm)[(k4 + 0) * 16 + tx];
            float4 w1 = ((const float4*)Wsm)[(k4 + 1) * 16 + tx];
            float4 w2 = ((const float4*)Wsm)[(k4 + 2) * 16 + tx];
            float4 w3 = ((const float4*)Wsm)[(k4 + 3) * 16 + tx];
            #define FMA4(ACC, AV)                                              \
                ACC.x += AV.x * w0.x; ACC.y += AV.x * w0.y;                    \
                ACC.z += AV.x * w0.z; ACC.w += AV.x * w0.w;                    \
                ACC.x += AV.y * w1.x; ACC.y += AV.y * w1.y;                    \
                ACC.z += AV.y * w1.z; ACC.w += AV.y * w1.w;                    \
                ACC.x += AV.z * w2.x; ACC.y += AV.z * w2.y;                    \
                ACC.z += AV.z * w2.z; ACC.w += AV.z * w2.w;                    \
                ACC.x += AV.w * w3.x; ACC.y += AV.w * w3.y;                    \
                ACC.z += AV.w * w3.z; ACC.w += AV.w * w3.w;
            FMA4(acc0, a0) FMA4(acc1, a1) FMA4(acc2, a2) FMA4(acc3, a3)
            #undef FMA4
        }
        __syncthreads();
    }

    float4 cv = *(const float4*)(g_c + 4 * tx);
    float4 accs[4] = {acc0, acc1, acc2, acc3};
    float4 ls = {0,0,0,0}, lq = {0,0,0,0};
    #pragma unroll
    for (int i = 0; i < 4; i++) {
        int gr = rowBase + 4 * ty + i;
        if (gr >= n) continue;
        float4 v = accs[i];
        v.x += cv.x; v.y += cv.y; v.z += cv.z; v.w += cv.w;
        if (FEAT) {
            v.x = fmaxf(v.x, 0.f); v.y = fmaxf(v.y, 0.f);
            v.z = fmaxf(v.z, 0.f); v.w = fmaxf(v.w, 0.f);
            *(float4*)(g_h + (long)gr * 64 + 4 * tx) = v;
            ls.x += v.x; ls.y += v.y; ls.z += v.z; ls.w += v.w;
            lq.x += v.x * v.x; lq.y += v.y * v.y;
            lq.z += v.z * v.z; lq.w += v.w * v.w;
        } else {
            *(float4*)(g_z + (long)gr * 64 + 4 * tx) = v;
        }
    }
    if (FEAT) {   // block-reduce partial stats over ty, write per-block slot
        __syncthreads();
        ((float4*)As)[t]  = ls;
        ((float4*)Wsm)[t] = lq;
        __syncthreads();
        if (ty == 0) {
            #pragma unroll
            for (int j = 1; j < 16; j++) {
                float4 a = ((float4*)As)[j * 16 + tx];
                float4 b = ((float4*)Wsm)[j * 16 + tx];
                ls.x += a.x; ls.y += a.y; ls.z += a.z; ls.w += a.w;
                lq.x += b.x; lq.y += b.y; lq.z += b.z; lq.w += b.w;
            }
            *(float4*)(g_psum + blockIdx.x * 64 + 4 * tx) = ls;
            *(float4*)(g_psq  + blockIdx.x * 64 + 4 * tx) = lq;
        }
    }
}

// ---------------- CSR gather aggregation ------------------------------------
// out_i = dis_i * (dis_i*z_i + sum_{s in in(i)} dis_s * z_s); h = relu(out+b)
// MODE 0: write g_h + per-block partial stats.  MODE 1: pool into gout.
template <int MODE>
__global__ void __launch_bounds__(256)
gather_kernel(const float* __restrict__ bias,
              const int* __restrict__ batch,
              float* __restrict__ gout) {
    const int t    = threadIdx.x;
    const int c    = t & 15;
    const int slot = t >> 4;
    float4 b4 = *(const float4*)(bias + 4 * c);
    float4 ls = {0,0,0,0}, lq = {0,0,0,0};

    for (int base = blockIdx.x * 16; base < Nn; base += gridDim.x * 16) {
        int i = base + slot;
        if (i < Nn) {
            int st = __ldg(g_off + i), en = __ldg(g_off + i + 1);
            float di = __ldg(g_dis + i);
            float4 acc = *(const float4*)(g_z + (long)i * 64 + 4 * c);
            acc.x *= di; acc.y *= di; acc.z *= di; acc.w *= di;
            for (int e = st; e < en; e++) {
                int s = __ldg(g_csr + e);
                float w = __ldg(g_dis + s);
                float4 v = *(const float4*)(g_z + (long)s * 64 + 4 * c);
                acc.x += w * v.x; acc.y += w * v.y;
                acc.z += w * v.z; acc.w += w * v.w;
            }
            float4 h;
            h.x = fmaxf(di * acc.x + b4.x, 0.f);
            h.y = fmaxf(di * acc.y + b4.y, 0.f);
            h.z = fmaxf(di * acc.z + b4.z, 0.f);
            h.w = fmaxf(di * acc.w + b4.w, 0.f);
            if (MODE == 0) {
                *(float4*)(g_h + (long)i * 64 + 4 * c) = h;
                ls.x += h.x; ls.y += h.y; ls.z += h.z; ls.w += h.w;
                lq.x += h.x * h.x; lq.y += h.y * h.y;
                lq.z += h.z * h.z; lq.w += h.w * h.w;
            } else {
                int g = __ldg(batch + i);
                red_add_v4(gout + (long)g * 64 + 4 * c, h);
            }
        }
    }

    if (MODE == 0) {
        __shared__ float4 shS[256], shQ[256];
        shS[t] = ls; shQ[t] = lq;
        __syncthreads();
        if (slot == 0) {
            #pragma unroll
            for (int j = 1; j < 16; j++) {
                float4 a = shS[j * 16 + c], b = shQ[j * 16 + c];
                ls.x += a.x; ls.y += a.y; ls.z += a.z; ls.w += a.w;
                lq.x += b.x; lq.y += b.y; lq.z += b.z; lq.w += b.w;
            }
            *(float4*)(g_psum + blockIdx.x * 64 + 4 * c) = ls;
            *(float4*)(g_psq  + blockIdx.x * 64 + 4 * c) = lq;
        }
    }
}

// ---------------- host-side symbol resolution -------------------------------
static float* sym_h() {
    static float* p = nullptr;
    if (!p) cudaGetSymbolAddress((void**)&p, g_h);
    return p;
}

// ---------------- launch ------------------------------------------------------
extern "C" void kernel_launch(void* const* d_in, const int* in_sizes, int n_in,
                              void* d_out, int out_size) {
    const float* x         = (const float*)d_in[0];
    const int*   ei        = (const int*)d_in[1];
    const int*   src       = ei;
    const int*   dst       = ei + Ee;
    const int*   batch     = (const int*)d_in[2];
    const float* bn_feat_g = (const float*)d_in[3];
    const float* bn_feat_b = (const float*)d_in[4];
    const float* W_feat    = (const float*)d_in[5];
    const float* b_feat    = (const float*)d_in[6];
    const float* bn_g      = (const float*)d_in[7];
    const float* bn_b      = (const float*)d_in[8];
    const float* Ws        = (const float*)d_in[9];
    const float* bs        = (const float*)d_in[10];
    float* gout = (float*)d_out;

    const float invN = 1.0f / (float)Nn;

    // ---- CSR build + dis ----
    zero_all_kernel<<<(Nn + 255) / 256, 256>>>();
    count_kernel<<<(Ee + 255) / 256, 256>>>(src, dst);
    scan1_kernel<<<SCAN_NB, SCAN_T>>>();
    scan2_kernel<<<1, 32>>>();
    scan3_kernel<<<SCAN_NB, SCAN_T>>>();
    fill_kernel<<<(Ee + 255) / 256, 256>>>(src, dst);
    dis_kernel<<<(Nn + 255) / 256, 256>>>();

    // ---- feature BN (atomic stats) + folded linear + relu + h0 stats ----
    {
        dim3 b(F_IN, 2);
        stats_x_kernel<<<256, b>>>(x);
    }
    fold_kernel<<<1, 256>>>(bn_feat_g, bn_feat_b, W_feat, b_feat,
                            F_IN, invN, 0);
    gemm_kernel<F_IN, true><<<GEMM_BLOCKS, 256>>>(x, Nn);   // h0 + partials

    // ---- 3 GCN layers ----
    int nPart = GEMM_BLOCKS;
    for (int i = 0; i < Ll; i++) {
        fold_kernel<<<1, 256>>>(bn_g + i * HID, bn_b + i * HID,
                                Ws + (long)i * HID * HID, nullptr,
                                HID, invN, nPart);
        gemm_kernel<HID, false><<<GEMM_BLOCKS, 256>>>(sym_h(), Nn);
        if (i < Ll - 1) {
            gather_kernel<0><<<GATHER_BLOCKS, 256>>>(bs + i * HID, nullptr,
                                                     nullptr);
            nPart = GATHER_BLOCKS;
        } else {
            cudaMemsetAsync(gout, 0, (size_t)Gg * HID * sizeof(float));
            gather_kernel<1><<<GATHER_BLOCKS, 256>>>(bs + i * HID, batch,
                                                     gout);
        }
    }
}